// round 4
// baseline (speedup 1.0000x reference)
#include <cuda_runtime.h>
#include <math.h>

#define NMAX 20000
#define EMAX 200000

// ---------------- scratch (static __device__; no cudaMalloc) ----------------
__device__ float g_pre[NMAX * 512];
__device__ float g_selfx[NMAX * 512];
__device__ float g_acc[NMAX * 512];
__device__ float g_xg[NMAX * 512];
__device__ float g_z[NMAX * 256];
__device__ float g_h[NMAX * 256];
__device__ float g_g[NMAX * 256];
__device__ float g_adst[NMAX * 32];
__device__ float g_ws1ab[128 * 32];

// ---------------- helpers ----------------------------------------------------
__device__ __forceinline__ float sspf(float v) {
    // softplus(v) - log(2), numerically stable
    float sp = (v > 0.f) ? (v + log1pf(expf(-v))) : log1pf(expf(v));
    return sp - 0.693147180559945309f;
}
__device__ __forceinline__ float siluf(float v) {
    return v / (1.f + expf(-v));
}
__device__ __forceinline__ void red_add_v4(float* addr, float a, float b, float c, float d) {
    asm volatile("red.global.add.v4.f32 [%0], {%1,%2,%3,%4};"
                 :: "l"(addr), "f"(a), "f"(b), "f"(c), "f"(d) : "memory");
}

// ---------------- ws1ab = W_s1[0:128] + W_s1[128:256] -----------------------
__global__ void k_prep(const float* __restrict__ W_s1, float* __restrict__ ws1ab) {
    int i = blockIdx.x * blockDim.x + threadIdx.x;
    if (i < 128 * 32) ws1ab[i] = W_s1[i] + W_s1[128 * 32 + i];
}

// ---------------- generic irrep_linear --------------------------------------
// Y[n, v]           = sum_u X[n,u]          * W0[u,v] + b0[v]   (+resid)
// Y[n, 128+3v+c]    = sum_u X[n,128+3u+c]   * W1[u,v]           (+resid)
// Optionally dual-writes to Y2.
__global__ void __launch_bounds__(256, 2) k_irrep(
    const float* __restrict__ X, const float* __restrict__ W0,
    const float* __restrict__ b0, const float* __restrict__ W1,
    float* __restrict__ Y, float* __restrict__ Y2,
    const float* __restrict__ resid, int nRows)
{
    extern __shared__ float sm[];
    float* Xs  = sm;               // 32*512
    float* W0s = sm + 32 * 512;    // 32*128
    float* W1s = W0s + 32 * 128;   // 32*128
    const int tid = threadIdx.x;
    const int row0 = blockIdx.x * 32;

    for (int i = tid; i < 32 * 512; i += 256) {
        int r = i >> 9, c = i & 511;
        int gr = row0 + r;
        Xs[i] = (gr < nRows) ? X[(size_t)gr * 512 + c] : 0.f;
    }
    const int vg = tid & 31;   // cols vg*4..+3
    const int ng = tid >> 5;   // rows ng*4..+3
    float a0[4][4] = {};
    float a1[4][12] = {};

    for (int kt = 0; kt < 4; kt++) {
        __syncthreads();
        for (int i = tid; i < 32 * 128; i += 256) {
            W0s[i] = W0[kt * 32 * 128 + i];
            W1s[i] = W1[kt * 32 * 128 + i];
        }
        __syncthreads();
#pragma unroll 4
        for (int uu = 0; uu < 32; uu++) {
            const int u = kt * 32 + uu;
            float4 w0 = *reinterpret_cast<float4*>(&W0s[uu * 128 + vg * 4]);
            float4 w1 = *reinterpret_cast<float4*>(&W1s[uu * 128 + vg * 4]);
            float w0a[4] = {w0.x, w0.y, w0.z, w0.w};
            float w1a[4] = {w1.x, w1.y, w1.z, w1.w};
#pragma unroll
            for (int ni = 0; ni < 4; ni++) {
                const float* xr = Xs + (ng * 4 + ni) * 512;
                float x0 = xr[u];
                float xa = xr[128 + u * 3 + 0];
                float xb = xr[128 + u * 3 + 1];
                float xc = xr[128 + u * 3 + 2];
#pragma unroll
                for (int vi = 0; vi < 4; vi++) {
                    a0[ni][vi]         += x0 * w0a[vi];
                    a1[ni][vi * 3 + 0] += xa * w1a[vi];
                    a1[ni][vi * 3 + 1] += xb * w1a[vi];
                    a1[ni][vi * 3 + 2] += xc * w1a[vi];
                }
            }
        }
    }
    float4 bb = *reinterpret_cast<const float4*>(&b0[vg * 4]);
    float bv[4] = {bb.x, bb.y, bb.z, bb.w};
#pragma unroll
    for (int ni = 0; ni < 4; ni++) {
        int n = row0 + ng * 4 + ni;
        if (n >= nRows) continue;
        size_t base = (size_t)n * 512;
        float4 o0; float* o0p = (float*)&o0;
#pragma unroll
        for (int vi = 0; vi < 4; vi++) {
            float v = a0[ni][vi] + bv[vi];
            if (resid) v += resid[base + vg * 4 + vi];
            o0p[vi] = v;
        }
        float4 ov[3]; float* ovp = (float*)ov;
#pragma unroll
        for (int j = 0; j < 12; j++) {
            float v = a1[ni][j];
            if (resid) v += resid[base + 128 + vg * 12 + j];
            ovp[j] = v;
        }
        *reinterpret_cast<float4*>(&Y[base + vg * 4]) = o0;
        *reinterpret_cast<float4*>(&Y[base + 128 + vg * 12 + 0]) = ov[0];
        *reinterpret_cast<float4*>(&Y[base + 128 + vg * 12 + 4]) = ov[1];
        *reinterpret_cast<float4*>(&Y[base + 128 + vg * 12 + 8]) = ov[2];
        if (Y2) {
            *reinterpret_cast<float4*>(&Y2[base + vg * 4]) = o0;
            *reinterpret_cast<float4*>(&Y2[base + 128 + vg * 12 + 0]) = ov[0];
            *reinterpret_cast<float4*>(&Y2[base + 128 + vg * 12 + 4]) = ov[1];
            *reinterpret_cast<float4*>(&Y2[base + 128 + vg * 12 + 8]) = ov[2];
        }
    }
}

// ---------------- a_dst = p0 @ ws1ab  ([N,128] @ [128,32]) -------------------
__global__ void __launch_bounds__(256) k_adst(
    const float* __restrict__ pre, const float* __restrict__ ws1ab,
    float* __restrict__ adst, int nRows)
{
    __shared__ float p0s[8 * 128];
    __shared__ float ws[128 * 32];
    const int tid = threadIdx.x;
    const int row0 = blockIdx.x * 8;
    for (int i = tid; i < 128 * 32; i += 256) ws[i] = ws1ab[i];
    for (int i = tid; i < 8 * 128; i += 256) {
        int r = i >> 7, c = i & 127;
        int gr = row0 + r;
        p0s[i] = (gr < nRows) ? pre[(size_t)gr * 512 + c] : 0.f;
    }
    __syncthreads();
    const int h = tid & 31, nl = tid >> 5;
    float acc = 0.f;
#pragma unroll 8
    for (int u = 0; u < 128; u++) acc += p0s[nl * 128 + u] * ws[u * 32 + h];
    int n = row0 + nl;
    if (n < nRows) adst[(size_t)n * 32 + h] = acc;
}

// ---------------- z = [x0, sqrt(mean_c x1^2)] --------------------------------
__global__ void k_znorm(const float* __restrict__ x, float* __restrict__ z, int nRows) {
    int t = blockIdx.x * blockDim.x + threadIdx.x;
    if (t >= nRows * 128) return;
    int n = t >> 7, u = t & 127;
    size_t b5 = (size_t)n * 512, b2 = (size_t)n * 256;
    z[b2 + u] = x[b5 + u];
    float a = x[b5 + 128 + u * 3 + 0];
    float b = x[b5 + 128 + u * 3 + 1];
    float c = x[b5 + 128 + u * 3 + 2];
    z[b2 + 128 + u] = sqrtf((a * a + b * b + c * c) * (1.f / 3.f));
}

// ---------------- dense 256x256 GEMM: Y = act(X @ W + b) ---------------------
__global__ void __launch_bounds__(256, 3) k_gemm256(
    const float* __restrict__ X, const float* __restrict__ W,
    const float* __restrict__ b, float* __restrict__ Y, int nRows, int act)
{
    extern __shared__ float sm[];
    float* Xs = sm;             // 32*256
    float* Ws = sm + 32 * 256;  // 32*256
    const int tid = threadIdx.x;
    const int row0 = blockIdx.x * 32;
    for (int i = tid; i < 32 * 256; i += 256) {
        int r = i >> 8, c = i & 255;
        int gr = row0 + r;
        Xs[i] = (gr < nRows) ? X[(size_t)gr * 256 + c] : 0.f;
    }
    const int vg = tid & 63;   // cols vg*4..+3
    const int ng = tid >> 6;   // rows ng*8..+7
    float acc[8][4] = {};
    for (int kt = 0; kt < 8; kt++) {
        __syncthreads();
        for (int i = tid; i < 32 * 256; i += 256) {
            int r = i >> 8, c = i & 255;
            Ws[i] = W[(size_t)(kt * 32 + r) * 256 + c];
        }
        __syncthreads();
#pragma unroll 4
        for (int uu = 0; uu < 32; uu++) {
            float4 w = *reinterpret_cast<float4*>(&Ws[uu * 256 + vg * 4]);
#pragma unroll
            for (int ni = 0; ni < 8; ni++) {
                float xv = Xs[(ng * 8 + ni) * 256 + kt * 32 + uu];
                acc[ni][0] += xv * w.x; acc[ni][1] += xv * w.y;
                acc[ni][2] += xv * w.z; acc[ni][3] += xv * w.w;
            }
        }
    }
    float4 bb = *reinterpret_cast<const float4*>(&b[vg * 4]);
    float bv[4] = {bb.x, bb.y, bb.z, bb.w};
#pragma unroll
    for (int ni = 0; ni < 8; ni++) {
        int n = row0 + ng * 8 + ni;
        if (n >= nRows) continue;
        float4 o; float* op = (float*)&o;
#pragma unroll
        for (int vi = 0; vi < 4; vi++) {
            float v = acc[ni][vi] + bv[vi];
            op[vi] = act ? siluf(v) : v;
        }
        *reinterpret_cast<float4*>(&Y[(size_t)n * 256 + vg * 4]) = o;
    }
}

// ---------------- xg = merge(g[:, :128], x1 * g[:, 128:, None]) --------------
__global__ void k_xg(const float* __restrict__ x, const float* __restrict__ g,
                     float* __restrict__ xg, int nRows) {
    int t = blockIdx.x * blockDim.x + threadIdx.x;
    if (t >= nRows * 128) return;
    int n = t >> 7, u = t & 127;
    size_t b5 = (size_t)n * 512, b2 = (size_t)n * 256;
    xg[b5 + u] = g[b2 + u];
    float gu = g[b2 + 128 + u];
    xg[b5 + 128 + u * 3 + 0] = x[b5 + 128 + u * 3 + 0] * gu;
    xg[b5 + 128 + u * 3 + 1] = x[b5 + 128 + u * 3 + 1] * gu;
    xg[b5 + 128 + u * 3 + 2] = x[b5 + 128 + u * 3 + 2] * gu;
}

// ---------------- edge kernel: one warp per edge -----------------------------
__global__ void __launch_bounds__(512, 1) k_edge(
    const float* __restrict__ pre, const float* __restrict__ adst,
    const float* __restrict__ selfx,
    const float* __restrict__ edge_sh, const float* __restrict__ edge_attr,
    const int* __restrict__ edge_index,
    const float* __restrict__ W_s1, const float* __restrict__ W_f1,
    const float* __restrict__ W_f2, const float* __restrict__ W_s2,
    float* __restrict__ acc_out, int E)
{
    extern __shared__ float sm[];
    float* sWf2  = sm;                   // 32*512
    float* sWs2  = sWf2 + 32 * 512;      // 32*512
    float* sWs1c = sWs2 + 32 * 512;      // 128*32
    float* sWf1  = sWs1c + 128 * 32;     // 32*32
    float* sIp   = sWf1 + 32 * 32;       // 16 warps * 128
    float* sH    = sIp + 16 * 128;       // 16 warps * 64
    const int tid = threadIdx.x;
    for (int i = tid; i < 32 * 512; i += 512) { sWf2[i] = W_f2[i]; sWs2[i] = W_s2[i]; }
    for (int i = tid; i < 128 * 32; i += 512) sWs1c[i] = W_s1[256 * 32 + i];
    for (int i = tid; i < 32 * 32; i += 512) sWf1[i] = W_f1[i];
    __syncthreads();
    const int warp = tid >> 5, lane = tid & 31;
    float* ip = sIp + warp * 128;
    float* hH = sH + warp * 64;
    const float inv3 = 1.f / 3.f;
    const float invs3 = 0.57735026918962576f;

    for (int e = blockIdx.x * 16 + warp; e < E; e += gridDim.x * 16) {
        const int dst = edge_index[e];
        const int src = edge_index[E + e];
        // ip1[u] = <p1[dst,u,:], p1[src,u,:]> / 3 ; lane owns u = 4*lane..+3
        const float* pd = pre + (size_t)dst * 512 + 128 + 12 * lane;
        const float* ps = pre + (size_t)src * 512 + 128 + 12 * lane;
        float4 d0 = *(const float4*)(pd);
        float4 d1 = *(const float4*)(pd + 4);
        float4 d2 = *(const float4*)(pd + 8);
        float4 s0 = *(const float4*)(ps);
        float4 s1 = *(const float4*)(ps + 4);
        float4 s2 = *(const float4*)(ps + 8);
        float4 ipv;
        ipv.x = (d0.x * s0.x + d0.y * s0.y + d0.z * s0.z) * inv3;
        ipv.y = (d0.w * s0.w + d1.x * s1.x + d1.y * s1.y) * inv3;
        ipv.z = (d1.z * s1.z + d1.w * s1.w + d2.x * s2.x) * inv3;
        ipv.w = (d2.y * s2.y + d2.z * s2.z + d2.w * s2.w) * inv3;
        *(float4*)(ip + 4 * lane) = ipv;
        __syncwarp();
        // h_s = ssp(a_dst[dst] + ip1 @ Ws1_c)   (32 outputs, one per lane)
        float accs = adst[(size_t)dst * 32 + lane];
#pragma unroll 8
        for (int u4 = 0; u4 < 32; u4++) {
            float4 iv = *(const float4*)(ip + u4 * 4);
            accs += iv.x * sWs1c[(u4 * 4 + 0) * 32 + lane];
            accs += iv.y * sWs1c[(u4 * 4 + 1) * 32 + lane];
            accs += iv.z * sWs1c[(u4 * 4 + 2) * 32 + lane];
            accs += iv.w * sWs1c[(u4 * 4 + 3) * 32 + lane];
        }
        float hs = sspf(accs);
        __syncwarp();
        // h_f = ssp(edge_attr[e] @ W_f1)
        ip[lane] = edge_attr[(size_t)e * 32 + lane];
        __syncwarp();
        float accf = 0.f;
#pragma unroll 8
        for (int a = 0; a < 32; a++) accf += ip[a] * sWf1[a * 32 + lane];
        hH[lane] = sspf(accf);
        hH[32 + lane] = hs;
        __syncwarp();
        // w = (h_f @ W_f2) * (h_s @ W_s2); lane owns cols j = sec*128 + 4*lane + i
        float af[16], as_[16];
#pragma unroll
        for (int t = 0; t < 16; t++) { af[t] = 0.f; as_[t] = 0.f; }
#pragma unroll 4
        for (int a = 0; a < 32; a++) {
            float f = hH[a], s = hH[32 + a];
            const float* wf = sWf2 + a * 512 + 4 * lane;
            const float* ws = sWs2 + a * 512 + 4 * lane;
#pragma unroll
            for (int sec = 0; sec < 4; sec++) {
                float4 vf = *(const float4*)(wf + sec * 128);
                float4 vs = *(const float4*)(ws + sec * 128);
                af[sec * 4 + 0] += f * vf.x; af[sec * 4 + 1] += f * vf.y;
                af[sec * 4 + 2] += f * vf.z; af[sec * 4 + 3] += f * vf.w;
                as_[sec * 4 + 0] += s * vs.x; as_[sec * 4 + 1] += s * vs.y;
                as_[sec * 4 + 2] += s * vs.z; as_[sec * 4 + 3] += s * vs.w;
            }
        }
        // edge features + scatter-add; lane owns u = 4*lane + i
        float4 shv = *(const float4*)(edge_sh + (size_t)e * 4);
        const float sh0 = shv.x, sh1x = shv.y, sh1y = shv.z, sh1z = shv.w;
        const float* xs = selfx + (size_t)src * 512;
        float* ao = acc_out + (size_t)dst * 512;
        float4 x0v = *(const float4*)(xs + 4 * lane);
        float4 xv0 = *(const float4*)(xs + 128 + 12 * lane);
        float4 xv1 = *(const float4*)(xs + 128 + 12 * lane + 4);
        float4 xv2 = *(const float4*)(xs + 128 + 12 * lane + 8);
        float x0e[4] = {x0v.x, x0v.y, x0v.z, x0v.w};
        float xa[4] = {xv0.x, xv0.w, xv1.z, xv2.y};
        float xb[4] = {xv0.y, xv1.x, xv1.w, xv2.z};
        float xc[4] = {xv0.z, xv1.y, xv2.x, xv2.w};
        float o0[4], oa[4], ob[4], oc[4];
#pragma unroll
        for (int i = 0; i < 4; i++) {
            float w1 = af[i]      * as_[i];
            float w2 = af[4 + i]  * as_[4 + i];
            float w3 = af[8 + i]  * as_[8 + i];
            float w4 = af[12 + i] * as_[12 + i];
            o0[i] = w1 * x0e[i] * sh0
                  + w4 * (xa[i] * sh1x + xb[i] * sh1y + xc[i] * sh1z) * invs3;
            oa[i] = w2 * x0e[i] * sh1x + w3 * xa[i] * sh0;
            ob[i] = w2 * x0e[i] * sh1y + w3 * xb[i] * sh0;
            oc[i] = w2 * x0e[i] * sh1z + w3 * xc[i] * sh0;
        }
        // scalar block: 16B-aligned (4*lane floats)
        red_add_v4(ao + 4 * lane, o0[0], o0[1], o0[2], o0[3]);
        // vector block: byte offset 512 + 48*lane -> 16B-aligned
        red_add_v4(ao + 128 + 12 * lane,     oa[0], ob[0], oc[0], oa[1]);
        red_add_v4(ao + 128 + 12 * lane + 4, ob[1], oc[1], oa[2], ob[2]);
        red_add_v4(ao + 128 + 12 * lane + 8, oc[2], oa[3], ob[3], oc[3]);
    }
}

// ---------------- host ------------------------------------------------------
extern "C" void kernel_launch(void* const* d_in, const int* in_sizes, int n_in,
                              void* d_out, int out_size) {
    const float* x         = (const float*)d_in[0];
    const float* edge_sh   = (const float*)d_in[1];
    const float* edge_attr = (const float*)d_in[2];
    const int*   edge_idx  = (const int*)  d_in[3];
    const float* W_pre0 = (const float*)d_in[4];
    const float* b_pre0 = (const float*)d_in[5];
    const float* W_pre1 = (const float*)d_in[6];
    const float* W_nd0  = (const float*)d_in[7];
    const float* b_nd0  = (const float*)d_in[8];
    const float* W_nd1  = (const float*)d_in[9];
    const float* W_g1   = (const float*)d_in[10];
    const float* b_g1   = (const float*)d_in[11];
    const float* W_g2   = (const float*)d_in[12];
    const float* b_g2   = (const float*)d_in[13];
    const float* W_f1   = (const float*)d_in[14];
    const float* W_f2   = (const float*)d_in[15];
    const float* W_s1   = (const float*)d_in[16];
    const float* W_s2   = (const float*)d_in[17];
    const float* W_o0   = (const float*)d_in[18];
    const float* b_o0   = (const float*)d_in[19];
    const float* W_o1   = (const float*)d_in[20];
    float* out = (float*)d_out;

    const int N = in_sizes[0] / 512;
    const int E = in_sizes[3] / 2;

    // scratch pointers
    float *pre, *selfx, *acc, *xg, *z, *h, *g, *adst, *ws1ab;
    cudaGetSymbolAddress((void**)&pre,   g_pre);
    cudaGetSymbolAddress((void**)&selfx, g_selfx);
    cudaGetSymbolAddress((void**)&acc,   g_acc);
    cudaGetSymbolAddress((void**)&xg,    g_xg);
    cudaGetSymbolAddress((void**)&z,     g_z);
    cudaGetSymbolAddress((void**)&h,     g_h);
    cudaGetSymbolAddress((void**)&g,     g_g);
    cudaGetSymbolAddress((void**)&adst,  g_adst);
    cudaGetSymbolAddress((void**)&ws1ab, g_ws1ab);

    const int SM_IRREP = (32 * 512 + 2 * 32 * 128) * 4;          // 98304 B
    const int SM_GEMM  = (2 * 32 * 256) * 4;                     // 65536 B
    const int SM_EDGE  = (2 * 32 * 512 + 128 * 32 + 32 * 32 + 16 * 128 + 16 * 64) * 4; // 163840 B
    cudaFuncSetAttribute(k_irrep,   cudaFuncAttributeMaxDynamicSharedMemorySize, SM_IRREP);
    cudaFuncSetAttribute(k_gemm256, cudaFuncAttributeMaxDynamicSharedMemorySize, SM_GEMM);
    cudaFuncSetAttribute(k_edge,    cudaFuncAttributeMaxDynamicSharedMemorySize, SM_EDGE);

    const int gIr = (N + 31) / 32;
    const int gEl = (N * 128 + 255) / 256;

    // 1) pre = irrep_linear(x, W_pre)
    k_irrep<<<gIr, 256, SM_IRREP>>>(x, W_pre0, b_pre0, W_pre1, pre, nullptr, nullptr, N);
    // 2) ws1ab, a_dst
    k_prep<<<16, 256>>>(W_s1, ws1ab);
    k_adst<<<(N + 7) / 8, 256>>>(pre, ws1ab, adst, N);
    // 3) gate path
    k_znorm<<<gEl, 256>>>(x, z, N);
    k_gemm256<<<gIr, 256, SM_GEMM>>>(z, W_g1, b_g1, h, N, 1);
    k_gemm256<<<gIr, 256, SM_GEMM>>>(h, W_g2, b_g2, g, N, 0);
    k_xg<<<gEl, 256>>>(x, g, xg, N);
    // 4) selfx = irrep_linear(xg, W_nd); dual-write accumulator init
    k_irrep<<<gIr, 256, SM_IRREP>>>(xg, W_nd0, b_nd0, W_nd1, selfx, acc, nullptr, N);
    // 5) edges: scatter-add into acc
    k_edge<<<148, 512, SM_EDGE>>>(pre, adst, selfx, edge_sh, edge_attr, edge_idx,
                                  W_s1, W_f1, W_f2, W_s2, acc, E);
    // 6) out = irrep_linear(acc, W_o) + x
    k_irrep<<<gIr, 256, SM_IRREP>>>(acc, W_o0, b_o0, W_o1, out, nullptr, x, N);
}

// round 5
// speedup vs baseline: 1.1552x; 1.1552x over previous
#include <cuda_runtime.h>
#include <math.h>
#include <stdint.h>

#define NMAX 20000
#define EMAX 200000

// ---------------- scratch (static __device__; no cudaMalloc) ----------------
__device__ float g_pre[NMAX * 512];
__device__ float g_selfx[NMAX * 512];
__device__ float g_acc[NMAX * 512];
__device__ float g_xg[NMAX * 512];
__device__ float g_z[NMAX * 256];
__device__ float g_h[NMAX * 256];
__device__ float g_g[NMAX * 256];
__device__ float g_adst[NMAX * 32];
__device__ float g_ws1ab[128 * 32];
__device__ float g_hf[EMAX * 32];
__device__ float g_hs[EMAX * 32];
__device__ float g_w[(size_t)EMAX * 512];

// ---------------- helpers ----------------------------------------------------
__device__ __forceinline__ float sspf(float v) {
    float sp = (v > 0.f) ? (v + log1pf(expf(-v))) : log1pf(expf(v));
    return sp - 0.693147180559945309f;
}
__device__ __forceinline__ float siluf(float v) {
    return v / (1.f + expf(-v));
}
__device__ __forceinline__ void red_add_v4(float* addr, float a, float b, float c, float d) {
    asm volatile("red.global.add.v4.f32 [%0], {%1,%2,%3,%4};"
                 :: "l"(addr), "f"(a), "f"(b), "f"(c), "f"(d) : "memory");
}
__device__ __forceinline__ uint32_t f2tf32(float f) {
    uint32_t u;
    asm("cvt.rna.tf32.f32 %0, %1;" : "=r"(u) : "f"(f));
    return u;
}
__device__ __forceinline__ void mma_tf32(float c[4], const uint32_t a[4],
                                         uint32_t b0, uint32_t b1) {
    asm volatile(
        "mma.sync.aligned.m16n8k8.row.col.f32.tf32.tf32.f32 "
        "{%0,%1,%2,%3}, {%4,%5,%6,%7}, {%8,%9}, {%0,%1,%2,%3};"
        : "+f"(c[0]), "+f"(c[1]), "+f"(c[2]), "+f"(c[3])
        : "r"(a[0]), "r"(a[1]), "r"(a[2]), "r"(a[3]), "r"(b0), "r"(b1));
}

// ---------------- ws1ab = W_s1[0:128] + W_s1[128:256] -----------------------
__global__ void k_prep(const float* __restrict__ W_s1, float* __restrict__ ws1ab) {
    int i = blockIdx.x * blockDim.x + threadIdx.x;
    if (i < 128 * 32) ws1ab[i] = W_s1[i] + W_s1[128 * 32 + i];
}

// ---------------- generic irrep_linear --------------------------------------
__global__ void __launch_bounds__(256, 2) k_irrep(
    const float* __restrict__ X, const float* __restrict__ W0,
    const float* __restrict__ b0, const float* __restrict__ W1,
    float* __restrict__ Y, float* __restrict__ Y2,
    const float* __restrict__ resid, int nRows)
{
    extern __shared__ float sm[];
    float* Xs  = sm;               // 32*512
    float* W0s = sm + 32 * 512;    // 32*128
    float* W1s = W0s + 32 * 128;   // 32*128
    const int tid = threadIdx.x;
    const int row0 = blockIdx.x * 32;

    for (int i = tid; i < 32 * 512; i += 256) {
        int r = i >> 9, c = i & 511;
        int gr = row0 + r;
        Xs[i] = (gr < nRows) ? X[(size_t)gr * 512 + c] : 0.f;
    }
    const int vg = tid & 31;
    const int ng = tid >> 5;
    float a0[4][4] = {};
    float a1[4][12] = {};

    for (int kt = 0; kt < 4; kt++) {
        __syncthreads();
        for (int i = tid; i < 32 * 128; i += 256) {
            W0s[i] = W0[kt * 32 * 128 + i];
            W1s[i] = W1[kt * 32 * 128 + i];
        }
        __syncthreads();
#pragma unroll 4
        for (int uu = 0; uu < 32; uu++) {
            const int u = kt * 32 + uu;
            float4 w0 = *reinterpret_cast<float4*>(&W0s[uu * 128 + vg * 4]);
            float4 w1 = *reinterpret_cast<float4*>(&W1s[uu * 128 + vg * 4]);
            float w0a[4] = {w0.x, w0.y, w0.z, w0.w};
            float w1a[4] = {w1.x, w1.y, w1.z, w1.w};
#pragma unroll
            for (int ni = 0; ni < 4; ni++) {
                const float* xr = Xs + (ng * 4 + ni) * 512;
                float x0 = xr[u];
                float xa = xr[128 + u * 3 + 0];
                float xb = xr[128 + u * 3 + 1];
                float xc = xr[128 + u * 3 + 2];
#pragma unroll
                for (int vi = 0; vi < 4; vi++) {
                    a0[ni][vi]         += x0 * w0a[vi];
                    a1[ni][vi * 3 + 0] += xa * w1a[vi];
                    a1[ni][vi * 3 + 1] += xb * w1a[vi];
                    a1[ni][vi * 3 + 2] += xc * w1a[vi];
                }
            }
        }
    }
    float4 bb = *reinterpret_cast<const float4*>(&b0[vg * 4]);
    float bv[4] = {bb.x, bb.y, bb.z, bb.w};
#pragma unroll
    for (int ni = 0; ni < 4; ni++) {
        int n = row0 + ng * 4 + ni;
        if (n >= nRows) continue;
        size_t base = (size_t)n * 512;
        float4 o0; float* o0p = (float*)&o0;
#pragma unroll
        for (int vi = 0; vi < 4; vi++) {
            float v = a0[ni][vi] + bv[vi];
            if (resid) v += resid[base + vg * 4 + vi];
            o0p[vi] = v;
        }
        float4 ov[3]; float* ovp = (float*)ov;
#pragma unroll
        for (int j = 0; j < 12; j++) {
            float v = a1[ni][j];
            if (resid) v += resid[base + 128 + vg * 12 + j];
            ovp[j] = v;
        }
        *reinterpret_cast<float4*>(&Y[base + vg * 4]) = o0;
        *reinterpret_cast<float4*>(&Y[base + 128 + vg * 12 + 0]) = ov[0];
        *reinterpret_cast<float4*>(&Y[base + 128 + vg * 12 + 4]) = ov[1];
        *reinterpret_cast<float4*>(&Y[base + 128 + vg * 12 + 8]) = ov[2];
        if (Y2) {
            *reinterpret_cast<float4*>(&Y2[base + vg * 4]) = o0;
            *reinterpret_cast<float4*>(&Y2[base + 128 + vg * 12 + 0]) = ov[0];
            *reinterpret_cast<float4*>(&Y2[base + 128 + vg * 12 + 4]) = ov[1];
            *reinterpret_cast<float4*>(&Y2[base + 128 + vg * 12 + 8]) = ov[2];
        }
    }
}

// ---------------- a_dst = p0 @ ws1ab ----------------------------------------
__global__ void __launch_bounds__(256) k_adst(
    const float* __restrict__ pre, const float* __restrict__ ws1ab,
    float* __restrict__ adst, int nRows)
{
    __shared__ float p0s[8 * 128];
    __shared__ float ws[128 * 32];
    const int tid = threadIdx.x;
    const int row0 = blockIdx.x * 8;
    for (int i = tid; i < 128 * 32; i += 256) ws[i] = ws1ab[i];
    for (int i = tid; i < 8 * 128; i += 256) {
        int r = i >> 7, c = i & 127;
        int gr = row0 + r;
        p0s[i] = (gr < nRows) ? pre[(size_t)gr * 512 + c] : 0.f;
    }
    __syncthreads();
    const int h = tid & 31, nl = tid >> 5;
    float acc = 0.f;
#pragma unroll 8
    for (int u = 0; u < 128; u++) acc += p0s[nl * 128 + u] * ws[u * 32 + h];
    int n = row0 + nl;
    if (n < nRows) adst[(size_t)n * 32 + h] = acc;
}

// ---------------- z = [x0, sqrt(mean_c x1^2)] --------------------------------
__global__ void k_znorm(const float* __restrict__ x, float* __restrict__ z, int nRows) {
    int t = blockIdx.x * blockDim.x + threadIdx.x;
    if (t >= nRows * 128) return;
    int n = t >> 7, u = t & 127;
    size_t b5 = (size_t)n * 512, b2 = (size_t)n * 256;
    z[b2 + u] = x[b5 + u];
    float a = x[b5 + 128 + u * 3 + 0];
    float b = x[b5 + 128 + u * 3 + 1];
    float c = x[b5 + 128 + u * 3 + 2];
    z[b2 + 128 + u] = sqrtf((a * a + b * b + c * c) * (1.f / 3.f));
}

// ---------------- dense 256x256 GEMM: Y = act(X @ W + b) ---------------------
__global__ void __launch_bounds__(256, 3) k_gemm256(
    const float* __restrict__ X, const float* __restrict__ W,
    const float* __restrict__ b, float* __restrict__ Y, int nRows, int act)
{
    extern __shared__ float sm[];
    float* Xs = sm;             // 32*256
    float* Ws = sm + 32 * 256;  // 32*256
    const int tid = threadIdx.x;
    const int row0 = blockIdx.x * 32;
    for (int i = tid; i < 32 * 256; i += 256) {
        int r = i >> 8, c = i & 255;
        int gr = row0 + r;
        Xs[i] = (gr < nRows) ? X[(size_t)gr * 256 + c] : 0.f;
    }
    const int vg = tid & 63;
    const int ng = tid >> 6;
    float acc[8][4] = {};
    for (int kt = 0; kt < 8; kt++) {
        __syncthreads();
        for (int i = tid; i < 32 * 256; i += 256) {
            int r = i >> 8, c = i & 255;
            Ws[i] = W[(size_t)(kt * 32 + r) * 256 + c];
        }
        __syncthreads();
#pragma unroll 4
        for (int uu = 0; uu < 32; uu++) {
            float4 w = *reinterpret_cast<float4*>(&Ws[uu * 256 + vg * 4]);
#pragma unroll
            for (int ni = 0; ni < 8; ni++) {
                float xv = Xs[(ng * 8 + ni) * 256 + kt * 32 + uu];
                acc[ni][0] += xv * w.x; acc[ni][1] += xv * w.y;
                acc[ni][2] += xv * w.z; acc[ni][3] += xv * w.w;
            }
        }
    }
    float4 bb = *reinterpret_cast<const float4*>(&b[vg * 4]);
    float bv[4] = {bb.x, bb.y, bb.z, bb.w};
#pragma unroll
    for (int ni = 0; ni < 8; ni++) {
        int n = row0 + ng * 8 + ni;
        if (n >= nRows) continue;
        float4 o; float* op = (float*)&o;
#pragma unroll
        for (int vi = 0; vi < 4; vi++) {
            float v = acc[ni][vi] + bv[vi];
            op[vi] = act ? siluf(v) : v;
        }
        *reinterpret_cast<float4*>(&Y[(size_t)n * 256 + vg * 4]) = o;
    }
}

// ---------------- xg = merge(g[:, :128], x1 * g[:, 128:, None]) --------------
__global__ void k_xg(const float* __restrict__ x, const float* __restrict__ g,
                     float* __restrict__ xg, int nRows) {
    int t = blockIdx.x * blockDim.x + threadIdx.x;
    if (t >= nRows * 128) return;
    int n = t >> 7, u = t & 127;
    size_t b5 = (size_t)n * 512, b2 = (size_t)n * 256;
    xg[b5 + u] = g[b2 + u];
    float gu = g[b2 + 128 + u];
    xg[b5 + 128 + u * 3 + 0] = x[b5 + 128 + u * 3 + 0] * gu;
    xg[b5 + 128 + u * 3 + 1] = x[b5 + 128 + u * 3 + 1] * gu;
    xg[b5 + 128 + u * 3 + 2] = x[b5 + 128 + u * 3 + 2] * gu;
}

// ---------------- k_h: hf = ssp(attr@W_f1), hs = ssp(a_dst + ip1@Ws1c) -------
__global__ void __launch_bounds__(256) k_h(
    const float* __restrict__ pre, const float* __restrict__ adst,
    const float* __restrict__ edge_attr, const int* __restrict__ edge_index,
    const float* __restrict__ W_s1, const float* __restrict__ W_f1,
    float* __restrict__ hf_out, float* __restrict__ hs_out, int E)
{
    __shared__ float sWs1c[128 * 32];
    __shared__ float sWf1[32 * 32];
    __shared__ float sIp[8 * 128];
    __shared__ float sAttr[8 * 32];
    const int tid = threadIdx.x;
    for (int i = tid; i < 128 * 32; i += 256) sWs1c[i] = W_s1[256 * 32 + i];
    for (int i = tid; i < 32 * 32; i += 256) sWf1[i] = W_f1[i];
    __syncthreads();
    const int warp = tid >> 5, lane = tid & 31;
    float* ip = sIp + warp * 128;
    float* at = sAttr + warp * 32;
    const float inv3 = 1.f / 3.f;

    for (int e = blockIdx.x * 8 + warp; e < E; e += gridDim.x * 8) {
        const int dst = edge_index[e];
        // ip1[u] per lane (u = 4*lane..+3)
        const int src = edge_index[E + e];
        const float* pd = pre + (size_t)dst * 512 + 128 + 12 * lane;
        const float* ps = pre + (size_t)src * 512 + 128 + 12 * lane;
        float4 d0 = *(const float4*)(pd);
        float4 d1 = *(const float4*)(pd + 4);
        float4 d2 = *(const float4*)(pd + 8);
        float4 s0 = *(const float4*)(ps);
        float4 s1 = *(const float4*)(ps + 4);
        float4 s2 = *(const float4*)(ps + 8);
        float4 ipv;
        ipv.x = (d0.x * s0.x + d0.y * s0.y + d0.z * s0.z) * inv3;
        ipv.y = (d0.w * s0.w + d1.x * s1.x + d1.y * s1.y) * inv3;
        ipv.z = (d1.z * s1.z + d1.w * s1.w + d2.x * s2.x) * inv3;
        ipv.w = (d2.y * s2.y + d2.z * s2.z + d2.w * s2.w) * inv3;
        *(float4*)(ip + 4 * lane) = ipv;
        at[lane] = edge_attr[(size_t)e * 32 + lane];
        __syncwarp();
        float accs = adst[(size_t)dst * 32 + lane];
#pragma unroll 8
        for (int u4 = 0; u4 < 32; u4++) {
            float4 iv = *(const float4*)(ip + u4 * 4);
            accs += iv.x * sWs1c[(u4 * 4 + 0) * 32 + lane];
            accs += iv.y * sWs1c[(u4 * 4 + 1) * 32 + lane];
            accs += iv.z * sWs1c[(u4 * 4 + 2) * 32 + lane];
            accs += iv.w * sWs1c[(u4 * 4 + 3) * 32 + lane];
        }
        float accf = 0.f;
#pragma unroll 8
        for (int a = 0; a < 32; a++) accf += at[a] * sWf1[a * 32 + lane];
        hf_out[(size_t)e * 32 + lane] = sspf(accf);
        hs_out[(size_t)e * 32 + lane] = sspf(accs);
        __syncwarp();
    }
}

// ---------------- k_w: w = (hf@W_f2) * (hs@W_s2) via tf32 mma ----------------
// block tile: 128 edges x 128 cols, K = 32. Pre-converted tf32 in smem.
#define AS 36
#define BS 136
__global__ void __launch_bounds__(256, 1) k_w(
    const float* __restrict__ hf, const float* __restrict__ hs,
    const float* __restrict__ Wf2, const float* __restrict__ Ws2,
    float* __restrict__ w, int E)
{
    extern __shared__ uint32_t smu[];
    uint32_t* sAf = smu;                 // 128*AS
    uint32_t* sAs = sAf + 128 * AS;
    uint32_t* sBf = sAs + 128 * AS;      // 32*BS
    uint32_t* sBs = sBf + 32 * BS;
    const int tid = threadIdx.x;
    const int e0 = blockIdx.x * 128;
    const int n0 = blockIdx.y * 128;

    for (int i = tid; i < 128 * 32; i += 256) {
        int r = i >> 5, c = i & 31;
        int e = e0 + r;
        float vf = (e < E) ? hf[(size_t)e * 32 + c] : 0.f;
        float vs = (e < E) ? hs[(size_t)e * 32 + c] : 0.f;
        sAf[r * AS + c] = f2tf32(vf);
        sAs[r * AS + c] = f2tf32(vs);
    }
    for (int i = tid; i < 32 * 128; i += 256) {
        int k = i >> 7, c = i & 127;
        sBf[k * BS + c] = f2tf32(Wf2[(size_t)k * 512 + n0 + c]);
        sBs[k * BS + c] = f2tf32(Ws2[(size_t)k * 512 + n0 + c]);
    }
    __syncthreads();

    const int warp = tid >> 5, lane = tid & 31;
    const int g = lane >> 2, t4 = lane & 3;
    const int m0 = warp * 16;

    uint32_t af[4][4], as_[4][4];
#pragma unroll
    for (int ks = 0; ks < 4; ks++) {
        const int k = ks * 8;
        af[ks][0] = sAf[(m0 + g) * AS + k + t4];
        af[ks][1] = sAf[(m0 + g + 8) * AS + k + t4];
        af[ks][2] = sAf[(m0 + g) * AS + k + t4 + 4];
        af[ks][3] = sAf[(m0 + g + 8) * AS + k + t4 + 4];
        as_[ks][0] = sAs[(m0 + g) * AS + k + t4];
        as_[ks][1] = sAs[(m0 + g + 8) * AS + k + t4];
        as_[ks][2] = sAs[(m0 + g) * AS + k + t4 + 4];
        as_[ks][3] = sAs[(m0 + g + 8) * AS + k + t4 + 4];
    }
    const int row0 = e0 + m0 + g;
    const int row1 = row0 + 8;

#pragma unroll 4
    for (int nt = 0; nt < 16; nt++) {
        float cf[4] = {0.f, 0.f, 0.f, 0.f};
        float cs[4] = {0.f, 0.f, 0.f, 0.f};
        const int nb = nt * 8 + g;
#pragma unroll
        for (int ks = 0; ks < 4; ks++) {
            const int k = ks * 8;
            uint32_t b0 = sBf[(k + t4) * BS + nb];
            uint32_t b1 = sBf[(k + t4 + 4) * BS + nb];
            mma_tf32(cf, af[ks], b0, b1);
            b0 = sBs[(k + t4) * BS + nb];
            b1 = sBs[(k + t4 + 4) * BS + nb];
            mma_tf32(cs, as_[ks], b0, b1);
        }
        const int col = n0 + nt * 8 + 2 * t4;
        if (row0 < E) {
            float2 v; v.x = cf[0] * cs[0]; v.y = cf[1] * cs[1];
            *reinterpret_cast<float2*>(&w[(size_t)row0 * 512 + col]) = v;
        }
        if (row1 < E) {
            float2 v; v.x = cf[2] * cs[2]; v.y = cf[3] * cs[3];
            *reinterpret_cast<float2*>(&w[(size_t)row1 * 512 + col]) = v;
        }
    }
}

// ---------------- k_scatter: edge features + segment sum ---------------------
__global__ void __launch_bounds__(256) k_scatter(
    const float* __restrict__ w, const float* __restrict__ selfx,
    const float* __restrict__ edge_sh, const int* __restrict__ edge_index,
    float* __restrict__ acc_out, int E)
{
    const int tid = threadIdx.x;
    const int warp = tid >> 5, lane = tid & 31;
    const float invs3 = 0.57735026918962576f;

    for (int e = blockIdx.x * 8 + warp; e < E; e += gridDim.x * 8) {
        const int dst = edge_index[e];
        const int src = edge_index[E + e];
        const float* we = w + (size_t)e * 512;
        float4 wq0 = *(const float4*)(we + 0   + 4 * lane);
        float4 wq1 = *(const float4*)(we + 128 + 4 * lane);
        float4 wq2 = *(const float4*)(we + 256 + 4 * lane);
        float4 wq3 = *(const float4*)(we + 384 + 4 * lane);
        float w1[4] = {wq0.x, wq0.y, wq0.z, wq0.w};
        float w2[4] = {wq1.x, wq1.y, wq1.z, wq1.w};
        float w3[4] = {wq2.x, wq2.y, wq2.z, wq2.w};
        float w4[4] = {wq3.x, wq3.y, wq3.z, wq3.w};

        float4 shv = *(const float4*)(edge_sh + (size_t)e * 4);
        const float sh0 = shv.x, sh1x = shv.y, sh1y = shv.z, sh1z = shv.w;
        const float* xs = selfx + (size_t)src * 512;
        float* ao = acc_out + (size_t)dst * 512;
        float4 x0v = *(const float4*)(xs + 4 * lane);
        float4 xv0 = *(const float4*)(xs + 128 + 12 * lane);
        float4 xv1 = *(const float4*)(xs + 128 + 12 * lane + 4);
        float4 xv2 = *(const float4*)(xs + 128 + 12 * lane + 8);
        float x0e[4] = {x0v.x, x0v.y, x0v.z, x0v.w};
        float xa[4] = {xv0.x, xv0.w, xv1.z, xv2.y};
        float xb[4] = {xv0.y, xv1.x, xv1.w, xv2.z};
        float xc[4] = {xv0.z, xv1.y, xv2.x, xv2.w};
        float o0[4], oa[4], ob[4], oc[4];
#pragma unroll
        for (int i = 0; i < 4; i++) {
            o0[i] = w1[i] * x0e[i] * sh0
                  + w4[i] * (xa[i] * sh1x + xb[i] * sh1y + xc[i] * sh1z) * invs3;
            oa[i] = w2[i] * x0e[i] * sh1x + w3[i] * xa[i] * sh0;
            ob[i] = w2[i] * x0e[i] * sh1y + w3[i] * xb[i] * sh0;
            oc[i] = w2[i] * x0e[i] * sh1z + w3[i] * xc[i] * sh0;
        }
        red_add_v4(ao + 4 * lane, o0[0], o0[1], o0[2], o0[3]);
        red_add_v4(ao + 128 + 12 * lane,     oa[0], ob[0], oc[0], oa[1]);
        red_add_v4(ao + 128 + 12 * lane + 4, ob[1], oc[1], oa[2], ob[2]);
        red_add_v4(ao + 128 + 12 * lane + 8, oc[2], oa[3], ob[3], oc[3]);
    }
}

// ---------------- host ------------------------------------------------------
extern "C" void kernel_launch(void* const* d_in, const int* in_sizes, int n_in,
                              void* d_out, int out_size) {
    const float* x         = (const float*)d_in[0];
    const float* edge_sh   = (const float*)d_in[1];
    const float* edge_attr = (const float*)d_in[2];
    const int*   edge_idx  = (const int*)  d_in[3];
    const float* W_pre0 = (const float*)d_in[4];
    const float* b_pre0 = (const float*)d_in[5];
    const float* W_pre1 = (const float*)d_in[6];
    const float* W_nd0  = (const float*)d_in[7];
    const float* b_nd0  = (const float*)d_in[8];
    const float* W_nd1  = (const float*)d_in[9];
    const float* W_g1   = (const float*)d_in[10];
    const float* b_g1   = (const float*)d_in[11];
    const float* W_g2   = (const float*)d_in[12];
    const float* b_g2   = (const float*)d_in[13];
    const float* W_f1   = (const float*)d_in[14];
    const float* W_f2   = (const float*)d_in[15];
    const float* W_s1   = (const float*)d_in[16];
    const float* W_s2   = (const float*)d_in[17];
    const float* W_o0   = (const float*)d_in[18];
    const float* b_o0   = (const float*)d_in[19];
    const float* W_o1   = (const float*)d_in[20];
    float* out = (float*)d_out;

    const int N = in_sizes[0] / 512;
    const int E = in_sizes[3] / 2;

    float *pre, *selfx, *acc, *xg, *z, *h, *g, *adst, *ws1ab, *hf, *hs, *wbuf;
    cudaGetSymbolAddress((void**)&pre,   g_pre);
    cudaGetSymbolAddress((void**)&selfx, g_selfx);
    cudaGetSymbolAddress((void**)&acc,   g_acc);
    cudaGetSymbolAddress((void**)&xg,    g_xg);
    cudaGetSymbolAddress((void**)&z,     g_z);
    cudaGetSymbolAddress((void**)&h,     g_h);
    cudaGetSymbolAddress((void**)&g,     g_g);
    cudaGetSymbolAddress((void**)&adst,  g_adst);
    cudaGetSymbolAddress((void**)&ws1ab, g_ws1ab);
    cudaGetSymbolAddress((void**)&hf,    g_hf);
    cudaGetSymbolAddress((void**)&hs,    g_hs);
    cudaGetSymbolAddress((void**)&wbuf,  g_w);

    const int SM_IRREP = (32 * 512 + 2 * 32 * 128) * 4;
    const int SM_GEMM  = (2 * 32 * 256) * 4;
    const int SM_W     = (2 * 128 * AS + 2 * 32 * BS) * 4;
    cudaFuncSetAttribute(k_irrep,   cudaFuncAttributeMaxDynamicSharedMemorySize, SM_IRREP);
    cudaFuncSetAttribute(k_gemm256, cudaFuncAttributeMaxDynamicSharedMemorySize, SM_GEMM);
    cudaFuncSetAttribute(k_w,       cudaFuncAttributeMaxDynamicSharedMemorySize, SM_W);

    const int gIr = (N + 31) / 32;
    const int gEl = (N * 128 + 255) / 256;

    // 1) pre = irrep_linear(x, W_pre)
    k_irrep<<<gIr, 256, SM_IRREP>>>(x, W_pre0, b_pre0, W_pre1, pre, nullptr, nullptr, N);
    // 2) ws1ab, a_dst, edge hidden activations
    k_prep<<<16, 256>>>(W_s1, ws1ab);
    k_adst<<<(N + 7) / 8, 256>>>(pre, ws1ab, adst, N);
    k_h<<<1184, 256>>>(pre, adst, edge_attr, edge_idx, W_s1, W_f1, hf, hs, E);
    // 3) w = (hf@W_f2) * (hs@W_s2) — tf32 tensor GEMM
    {
        dim3 grid((E + 127) / 128, 4);
        k_w<<<grid, 256, SM_W>>>(hf, hs, W_f2, W_s2, wbuf, E);
    }
    // 4) gate path
    k_znorm<<<gEl, 256>>>(x, z, N);
    k_gemm256<<<gIr, 256, SM_GEMM>>>(z, W_g1, b_g1, h, N, 1);
    k_gemm256<<<gIr, 256, SM_GEMM>>>(h, W_g2, b_g2, g, N, 0);
    k_xg<<<gEl, 256>>>(x, g, xg, N);
    // 5) selfx = irrep_linear(xg, W_nd); dual-write accumulator init
    k_irrep<<<gIr, 256, SM_IRREP>>>(xg, W_nd0, b_nd0, W_nd1, selfx, acc, nullptr, N);
    // 6) edge features + segment sum into acc
    k_scatter<<<1184, 256>>>(wbuf, selfx, edge_sh, edge_idx, acc, E);
    // 7) out = irrep_linear(acc, W_o) + x
    k_irrep<<<gIr, 256, SM_IRREP>>>(acc, W_o0, b_o0, W_o1, out, nullptr, x, N);
}